// round 4
// baseline (speedup 1.0000x reference)
#include <cuda_runtime.h>
#include <math.h>

#define NN 50000
#define NE 600000
#define HD 128
#define NG 64
#define HID (NG * 256)

// ---------------- scratch (static device globals; no runtime allocation) ----
__device__ __align__(16) float g_deg[NN];        // degree, then reused as dinv
__device__ __align__(16) float g_self[NN];       // self-loop norm = 2 * dinv^2
__device__ __align__(16) int   g_cnt[NN];        // in-degree (edges only)
__device__ __align__(16) int   g_ptr[NN + 1];    // CSR row pointers (by dst)
__device__ __align__(16) int   g_cur[NN];        // scatter cursors
__device__ __align__(16) int   g_srcA[NE];       // CSR: source node per slot
__device__ __align__(16) float g_normA[NE];      // CSR: edge norm per slot
__device__ __align__(16) float g_t[(size_t)NN * HD];   // GEMM output
__device__ __align__(16) float g_hA[(size_t)NN * HD];  // ping
__device__ __align__(16) float g_hB[(size_t)NN * HD];  // pong
__device__ __align__(16) float g_hidden[HID];          // readout [64,256]
__device__ __align__(16) float g_out[NG];              // final   [64,1]
__device__ int g_gs[NG], g_ge[NG];                     // per-graph node ranges

// ---------------- setup kernels ---------------------------------------------
__global__ void k_init() {
    int i = blockIdx.x * blockDim.x + threadIdx.x;
    if (i < NN) { g_deg[i] = 2.0f; g_cnt[i] = 0; }   // self-loop weight 2.0
    if (i < NG) { g_gs[i] = 0; g_ge[i] = 0; }
}

__global__ void k_deg(const int* __restrict__ ei, const float* __restrict__ ew) {
    int i = blockIdx.x * blockDim.x + threadIdx.x;
    if (i >= NE) return;
    int d = ei[NE + i];
    if ((unsigned)d >= NN) return;          // defensive: never crash
    atomicAdd(&g_deg[d], ew[i]);
    atomicAdd(&g_cnt[d], 1);
}

__global__ void k_dinv() {
    int i = blockIdx.x * blockDim.x + threadIdx.x;
    if (i >= NN) return;
    float dv = rsqrtf(g_deg[i]);   // deg >= 2 always (self-loop)
    g_deg[i] = dv;
    g_self[i] = 2.0f * dv * dv;
}

// single-block exclusive scan of g_cnt into g_ptr (and init cursors)
__global__ void k_scan() {
    __shared__ int sh[1024];
    const int tid = threadIdx.x;
    const int C = (NN + 1023) / 1024;
    int start = tid * C;
    int end = start + C; if (end > NN) end = NN;
    if (start > NN) start = NN;
    int s = 0;
    for (int i = start; i < end; i++) s += g_cnt[i];
    sh[tid] = s;
    __syncthreads();
    for (int off = 1; off < 1024; off <<= 1) {
        int v = (tid >= off) ? sh[tid - off] : 0;
        __syncthreads();
        sh[tid] += v;
        __syncthreads();
    }
    int run = sh[tid] - s;   // exclusive prefix at chunk start
    for (int i = start; i < end; i++) {
        g_ptr[i] = run;
        g_cur[i] = run;
        run += g_cnt[i];
    }
    if (tid == 1023) g_ptr[NN] = sh[1023];
}

__global__ void k_scatter(const int* __restrict__ ei, const float* __restrict__ ew) {
    int i = blockIdx.x * blockDim.x + threadIdx.x;
    if (i >= NE) return;
    int s = ei[i];
    int d = ei[NE + i];
    if ((unsigned)s >= NN || (unsigned)d >= NN) return;   // defensive
    int pos = atomicAdd(&g_cur[d], 1);
    if ((unsigned)pos >= NE) return;                      // defensive
    g_srcA[pos] = s;
    g_normA[pos] = g_deg[s] * ew[i] * g_deg[d];   // dinv[src]*w*dinv[dst]
}

__global__ void k_bounds(const int* __restrict__ batch) {
    int i = blockIdx.x * blockDim.x + threadIdx.x;
    if (i >= NN) return;
    int g = batch[i];
    if ((unsigned)g >= NG) return;                        // defensive
    if (i == 0 || batch[i - 1] != g) g_gs[g] = i;
    if (i == NN - 1 || batch[i + 1] != g) g_ge[g] = i + 1;
}

// ---------------- dense GEMM: O[n,128] = A[n,128] @ W[128,128] --------------
#define GEMM_SMEM ((128 * 128 + 128 * 68) * (int)sizeof(float))

__global__ void k_gemm(const float* __restrict__ A, const float* __restrict__ W,
                       float* __restrict__ O, int nrows) {
    extern __shared__ float sm[];
    float* Ws = sm;             // [128][128]
    float* As = sm + 128 * 128; // [128 k][68 rows], 64 used
    const int STR = 68;
    const int tid = threadIdx.x;
    const int row0 = blockIdx.x * 64;

    for (int i = tid; i < 128 * 128 / 4; i += 256)
        ((float4*)Ws)[i] = ((const float4*)W)[i];
    for (int idx = tid; idx < 64 * 128; idx += 256) {
        int r = idx >> 7, k = idx & 127;
        int gr = row0 + r;
        As[k * STR + r] = (gr < nrows) ? A[(size_t)gr * HD + k] : 0.0f;
    }
    __syncthreads();

    const int ty = tid >> 5;       // 0..7 -> rows ty*8..ty*8+7
    const int tx = tid & 31;       // cols tx*4..tx*4+3
    float4 acc[8];
#pragma unroll
    for (int r = 0; r < 8; r++) acc[r] = make_float4(0.f, 0.f, 0.f, 0.f);

    const float* arow = As + ty * 8;
#pragma unroll 8
    for (int k = 0; k < 128; k++) {
        float4 b = *(const float4*)(Ws + k * 128 + tx * 4);
        float av[8];
        *(float4*)&av[0] = *(const float4*)(arow + k * STR);
        *(float4*)&av[4] = *(const float4*)(arow + k * STR + 4);
#pragma unroll
        for (int r = 0; r < 8; r++) {
            acc[r].x += av[r] * b.x;
            acc[r].y += av[r] * b.y;
            acc[r].z += av[r] * b.z;
            acc[r].w += av[r] * b.w;
        }
    }
#pragma unroll
    for (int r = 0; r < 8; r++) {
        int gr = row0 + ty * 8 + r;
        if (gr < nrows) *(float4*)(O + (size_t)gr * HD + tx * 4) = acc[r];
    }
}

// ---------------- aggregation: one warp per destination node ----------------
__global__ void k_aggr(const float* __restrict__ T, const float* __restrict__ bias,
                       float* __restrict__ Hout) {
    int gw = (blockIdx.x * blockDim.x + threadIdx.x) >> 5;
    if (gw >= NN) return;
    const int lane = threadIdx.x & 31;
    const int c = lane << 2;

    float sn = g_self[gw];
    float4 t0 = *(const float4*)(T + (size_t)gw * HD + c);
    float4 acc = make_float4(t0.x * sn, t0.y * sn, t0.z * sn, t0.w * sn);

    int e = g_ptr[gw];
    const int e1 = g_ptr[gw + 1];
    for (; e + 3 < e1; e += 4) {
        int s0 = g_srcA[e], s1 = g_srcA[e + 1], s2 = g_srcA[e + 2], s3 = g_srcA[e + 3];
        float w0 = g_normA[e], w1 = g_normA[e + 1], w2 = g_normA[e + 2], w3 = g_normA[e + 3];
        float4 v0 = *(const float4*)(T + (size_t)s0 * HD + c);
        float4 v1 = *(const float4*)(T + (size_t)s1 * HD + c);
        float4 v2 = *(const float4*)(T + (size_t)s2 * HD + c);
        float4 v3 = *(const float4*)(T + (size_t)s3 * HD + c);
        acc.x += w0 * v0.x + w1 * v1.x + w2 * v2.x + w3 * v3.x;
        acc.y += w0 * v0.y + w1 * v1.y + w2 * v2.y + w3 * v3.y;
        acc.z += w0 * v0.z + w1 * v1.z + w2 * v2.z + w3 * v3.z;
        acc.w += w0 * v0.w + w1 * v1.w + w2 * v2.w + w3 * v3.w;
    }
    for (; e < e1; e++) {
        int s = g_srcA[e];
        float w = g_normA[e];
        float4 v = *(const float4*)(T + (size_t)s * HD + c);
        acc.x += w * v.x; acc.y += w * v.y; acc.z += w * v.z; acc.w += w * v.w;
    }
    float4 bb = *(const float4*)(bias + c);
    float4 o;
    o.x = tanhf(acc.x + bb.x);
    o.y = tanhf(acc.y + bb.y);
    o.z = tanhf(acc.z + bb.z);
    o.w = tanhf(acc.w + bb.w);
    *(float4*)(Hout + (size_t)gw * HD + c) = o;
}

// ---------------- readout ----------------------------------------------------
__global__ void k_readout(const float* __restrict__ Hl) {
    int g = blockIdx.x;
    int c = threadIdx.x;   // 128
    int s = g_gs[g], e = g_ge[g];
    float vmax = -INFINITY, vsum = 0.0f;
    for (int i = s; i < e; i++) {
        float v = Hl[(size_t)i * HD + c];
        vmax = fmaxf(vmax, v);
        vsum += v;
    }
    int cnt = e - s;
    g_hidden[(size_t)g * 256 + c] = (cnt > 0) ? vmax : 0.0f;
    g_hidden[(size_t)g * 256 + 128 + c] = vsum / fmaxf((float)cnt, 1.0f);
}

__global__ void k_final(const float* __restrict__ Wout, const float* __restrict__ bout) {
    __shared__ float red[256];
    int g = blockIdx.x, t = threadIdx.x;
    red[t] = g_hidden[(size_t)g * 256 + t] * Wout[t];
    __syncthreads();
    for (int off = 128; off > 0; off >>= 1) {
        if (t < off) red[t] += red[t + off];
        __syncthreads();
    }
    if (t == 0) g_out[g] = red[0] + bout[0];
}

// ---------------- emit: kernel copy into d_out (graph-capture safe) ----------
__global__ void k_emit(float* __restrict__ out, int out_size) {
    int i = blockIdx.x * blockDim.x + threadIdx.x;
    if (i >= out_size) return;
    float v;
    if (out_size >= NG + HID) {
        v = (i < NG) ? g_out[i] : g_hidden[i - NG];
    } else if (out_size == HID) {
        v = g_hidden[i];
    } else {
        v = (i < NG) ? g_out[i] : 0.0f;
    }
    out[i] = v;
}

// ---------------- launch -----------------------------------------------------
extern "C" void kernel_launch(void* const* d_in, const int* in_sizes, int n_in,
                              void* d_out, int out_size) {
    const float* x     = (const float*)d_in[0];
    const int*   ei    = (const int*)d_in[1];      // int32 (JAX x64 disabled)
    const int*   batch = (const int*)d_in[2];      // int32
    const float* ew    = (const float*)d_in[3];
    const float* W[4] = { (const float*)d_in[4], (const float*)d_in[6],
                          (const float*)d_in[8], (const float*)d_in[10] };
    const float* B[4] = { (const float*)d_in[5], (const float*)d_in[7],
                          (const float*)d_in[9], (const float*)d_in[11] };
    const float* Wout = (const float*)d_in[12];
    const float* bout = (const float*)d_in[13];

    cudaFuncSetAttribute(k_gemm, cudaFuncAttributeMaxDynamicSharedMemorySize, GEMM_SMEM);

    float *tbuf, *hA, *hB;
    cudaGetSymbolAddress((void**)&tbuf, g_t);
    cudaGetSymbolAddress((void**)&hA, g_hA);
    cudaGetSymbolAddress((void**)&hB, g_hB);

    k_init<<<(NN + 255) / 256, 256>>>();
    k_deg<<<(NE + 255) / 256, 256>>>(ei, ew);
    k_dinv<<<(NN + 255) / 256, 256>>>();
    k_scan<<<1, 1024>>>();
    k_scatter<<<(NE + 255) / 256, 256>>>(ei, ew);
    k_bounds<<<(NN + 255) / 256, 256>>>(batch);

    const int gemm_grid = (NN + 63) / 64;
    const int aggr_grid = (NN * 32 + 255) / 256;

    const float* cur = x;
    float* ping[4] = { hA, hB, hA, hB };
    for (int l = 0; l < 4; l++) {
        k_gemm<<<gemm_grid, 256, GEMM_SMEM>>>(cur, W[l], tbuf, NN);
        k_aggr<<<aggr_grid, 256>>>(tbuf, B[l], ping[l]);
        cur = ping[l];
    }

    k_readout<<<NG, 128>>>(cur);
    k_final<<<NG, 256>>>(Wout, bout);
    k_emit<<<(out_size + 255) / 256, 256>>>((float*)d_out, out_size);
}

// round 5
// speedup vs baseline: 1.1867x; 1.1867x over previous
#include <cuda_runtime.h>
#include <math.h>

#define NN 50000
#define NE 600000
#define HD 128
#define NG 64
#define HID (NG * 256)
#define SCAN_B 256
#define NBLK ((NN + SCAN_B - 1) / SCAN_B)   // 196

// ---------------- scratch (static device globals; no runtime allocation) ----
__device__ __align__(16) float g_deg[NN];        // degree, then reused as dinv
__device__ __align__(16) float g_self[NN];       // self-loop norm = 2 * dinv^2
__device__ __align__(16) int   g_cnt[NN];        // in-degree (edges only)
__device__ __align__(16) int   g_ptr[NN + 1];    // CSR row pointers (by dst)
__device__ __align__(16) int   g_cur[NN];        // scatter cursors
__device__ __align__(16) int   g_bsum[NBLK];     // per-block count sums
__device__ __align__(16) int   g_boff[NBLK];     // exclusive block offsets
__device__ __align__(16) int   g_srcA[NE];       // CSR: source node per slot
__device__ __align__(16) float g_normA[NE];      // CSR: edge norm per slot
__device__ __align__(16) float g_t[(size_t)NN * HD];   // GEMM output
__device__ __align__(16) float g_hA[(size_t)NN * HD];  // ping
__device__ __align__(16) float g_hB[(size_t)NN * HD];  // pong
__device__ __align__(16) float g_hidden[HID];          // readout [64,256]
__device__ __align__(16) float g_out[NG];              // final   [64,1]
__device__ int g_gs[NG], g_ge[NG];                     // per-graph node ranges

// ---------------- setup kernels ---------------------------------------------
__global__ void k_init() {
    int i = blockIdx.x * blockDim.x + threadIdx.x;
    if (i < NN) { g_deg[i] = 2.0f; g_cnt[i] = 0; }   // self-loop weight 2.0
    if (i < NG) { g_gs[i] = 0; g_ge[i] = 0; }
}

__global__ void k_deg(const int* __restrict__ ei, const float* __restrict__ ew) {
    int i = blockIdx.x * blockDim.x + threadIdx.x;
    if (i >= NE) return;
    int d = ei[NE + i];
    if ((unsigned)d >= NN) return;          // defensive
    atomicAdd(&g_deg[d], ew[i]);
    atomicAdd(&g_cnt[d], 1);
}

__global__ void k_dinv() {
    int i = blockIdx.x * blockDim.x + threadIdx.x;
    if (i >= NN) return;
    float dv = rsqrtf(g_deg[i]);   // deg >= 2 always (self-loop)
    g_deg[i] = dv;
    g_self[i] = 2.0f * dv * dv;
}

// ---------------- 3-phase exclusive scan of g_cnt into g_ptr ----------------
__global__ void k_bsum() {
    __shared__ int sh[SCAN_B];
    int i = blockIdx.x * SCAN_B + threadIdx.x;
    sh[threadIdx.x] = (i < NN) ? g_cnt[i] : 0;
    __syncthreads();
    for (int off = SCAN_B / 2; off > 0; off >>= 1) {
        if (threadIdx.x < off) sh[threadIdx.x] += sh[threadIdx.x + off];
        __syncthreads();
    }
    if (threadIdx.x == 0) g_bsum[blockIdx.x] = sh[0];
}

__global__ void k_bscan() {   // one block, 256 threads >= NBLK
    __shared__ int sh[SCAN_B];
    int t = threadIdx.x;
    int v = (t < NBLK) ? g_bsum[t] : 0;
    sh[t] = v;
    __syncthreads();
    for (int off = 1; off < SCAN_B; off <<= 1) {
        int u = (t >= off) ? sh[t - off] : 0;
        __syncthreads();
        sh[t] += u;
        __syncthreads();
    }
    if (t < NBLK) g_boff[t] = sh[t] - v;       // exclusive
    if (t == NBLK - 1) g_ptr[NN] = sh[t];      // total
}

__global__ void k_ptr() {
    __shared__ int sh[SCAN_B];
    int i = blockIdx.x * SCAN_B + threadIdx.x;
    int t = threadIdx.x;
    int v = (i < NN) ? g_cnt[i] : 0;
    sh[t] = v;
    __syncthreads();
    for (int off = 1; off < SCAN_B; off <<= 1) {
        int u = (t >= off) ? sh[t - off] : 0;
        __syncthreads();
        sh[t] += u;
        __syncthreads();
    }
    if (i < NN) {
        int p = g_boff[blockIdx.x] + sh[t] - v;   // exclusive prefix
        g_ptr[i] = p;
        g_cur[i] = p;
    }
}

__global__ void k_scatter(const int* __restrict__ ei, const float* __restrict__ ew) {
    int i = blockIdx.x * blockDim.x + threadIdx.x;
    if (i >= NE) return;
    int s = ei[i];
    int d = ei[NE + i];
    if ((unsigned)s >= NN || (unsigned)d >= NN) return;   // defensive
    int pos = atomicAdd(&g_cur[d], 1);
    if ((unsigned)pos >= NE) return;                      // defensive
    g_srcA[pos] = s;
    g_normA[pos] = g_deg[s] * ew[i] * g_deg[d];   // dinv[src]*w*dinv[dst]
}

__global__ void k_bounds(const int* __restrict__ batch) {
    int i = blockIdx.x * blockDim.x + threadIdx.x;
    if (i >= NN) return;
    int g = batch[i];
    if ((unsigned)g >= NG) return;                        // defensive
    if (i == 0 || batch[i - 1] != g) g_gs[g] = i;
    if (i == NN - 1 || batch[i + 1] != g) g_ge[g] = i + 1;
}

// ---------------- dense GEMM: O[n,128] = A[n,128] @ W[128,128] --------------
#define GEMM_SMEM ((128 * 128 + 128 * 68) * (int)sizeof(float))

__global__ void k_gemm(const float* __restrict__ A, const float* __restrict__ W,
                       float* __restrict__ O, int nrows) {
    extern __shared__ float sm[];
    float* Ws = sm;             // [128][128]
    float* As = sm + 128 * 128; // [128 k][68 rows], 64 used
    const int STR = 68;
    const int tid = threadIdx.x;
    const int row0 = blockIdx.x * 64;

    for (int i = tid; i < 128 * 128 / 4; i += 256)
        ((float4*)Ws)[i] = ((const float4*)W)[i];
    for (int idx = tid; idx < 64 * 128; idx += 256) {
        int r = idx >> 7, k = idx & 127;
        int gr = row0 + r;
        As[k * STR + r] = (gr < nrows) ? A[(size_t)gr * HD + k] : 0.0f;
    }
    __syncthreads();

    const int ty = tid >> 5;       // rows ty*8..ty*8+7
    const int tx = tid & 31;       // cols tx*4..tx*4+3
    float4 acc[8];
#pragma unroll
    for (int r = 0; r < 8; r++) acc[r] = make_float4(0.f, 0.f, 0.f, 0.f);

    const float* arow = As + ty * 8;
#pragma unroll 8
    for (int k = 0; k < 128; k++) {
        float4 b = *(const float4*)(Ws + k * 128 + tx * 4);
        float av[8];
        *(float4*)&av[0] = *(const float4*)(arow + k * STR);
        *(float4*)&av[4] = *(const float4*)(arow + k * STR + 4);
#pragma unroll
        for (int r = 0; r < 8; r++) {
            acc[r].x += av[r] * b.x;
            acc[r].y += av[r] * b.y;
            acc[r].z += av[r] * b.z;
            acc[r].w += av[r] * b.w;
        }
    }
#pragma unroll
    for (int r = 0; r < 8; r++) {
        int gr = row0 + ty * 8 + r;
        if (gr < nrows) *(float4*)(O + (size_t)gr * HD + tx * 4) = acc[r];
    }
}

// ---------------- aggregation: one warp per destination node ----------------
__global__ void k_aggr(const float* __restrict__ T, const float* __restrict__ bias,
                       float* __restrict__ Hout) {
    int gw = (blockIdx.x * blockDim.x + threadIdx.x) >> 5;
    if (gw >= NN) return;
    const int lane = threadIdx.x & 31;
    const int c = lane << 2;

    float sn = g_self[gw];
    float4 t0 = *(const float4*)(T + (size_t)gw * HD + c);
    float4 acc = make_float4(t0.x * sn, t0.y * sn, t0.z * sn, t0.w * sn);

    int e = g_ptr[gw];
    const int e1 = g_ptr[gw + 1];
    for (; e + 3 < e1; e += 4) {
        int s0 = g_srcA[e], s1 = g_srcA[e + 1], s2 = g_srcA[e + 2], s3 = g_srcA[e + 3];
        float w0 = g_normA[e], w1 = g_normA[e + 1], w2 = g_normA[e + 2], w3 = g_normA[e + 3];
        float4 v0 = *(const float4*)(T + (size_t)s0 * HD + c);
        float4 v1 = *(const float4*)(T + (size_t)s1 * HD + c);
        float4 v2 = *(const float4*)(T + (size_t)s2 * HD + c);
        float4 v3 = *(const float4*)(T + (size_t)s3 * HD + c);
        acc.x += w0 * v0.x + w1 * v1.x + w2 * v2.x + w3 * v3.x;
        acc.y += w0 * v0.y + w1 * v1.y + w2 * v2.y + w3 * v3.y;
        acc.z += w0 * v0.z + w1 * v1.z + w2 * v2.z + w3 * v3.z;
        acc.w += w0 * v0.w + w1 * v1.w + w2 * v2.w + w3 * v3.w;
    }
    for (; e < e1; e++) {
        int s = g_srcA[e];
        float w = g_normA[e];
        float4 v = *(const float4*)(T + (size_t)s * HD + c);
        acc.x += w * v.x; acc.y += w * v.y; acc.z += w * v.z; acc.w += w * v.w;
    }
    float4 bb = *(const float4*)(bias + c);
    float4 o;
    o.x = tanhf(acc.x + bb.x);
    o.y = tanhf(acc.y + bb.y);
    o.z = tanhf(acc.z + bb.z);
    o.w = tanhf(acc.w + bb.w);
    *(float4*)(Hout + (size_t)gw * HD + c) = o;
}

// ---------------- readout ----------------------------------------------------
__global__ void k_readout(const float* __restrict__ Hl) {
    int g = blockIdx.x;
    int c = threadIdx.x;   // 128
    int s = g_gs[g], e = g_ge[g];
    float vmax = -INFINITY, vsum = 0.0f;
    for (int i = s; i < e; i++) {
        float v = Hl[(size_t)i * HD + c];
        vmax = fmaxf(vmax, v);
        vsum += v;
    }
    int cnt = e - s;
    g_hidden[(size_t)g * 256 + c] = (cnt > 0) ? vmax : 0.0f;
    g_hidden[(size_t)g * 256 + 128 + c] = vsum / fmaxf((float)cnt, 1.0f);
}

__global__ void k_final(const float* __restrict__ Wout, const float* __restrict__ bout) {
    __shared__ float red[256];
    int g = blockIdx.x, t = threadIdx.x;
    red[t] = g_hidden[(size_t)g * 256 + t] * Wout[t];
    __syncthreads();
    for (int off = 128; off > 0; off >>= 1) {
        if (t < off) red[t] += red[t + off];
        __syncthreads();
    }
    if (t == 0) g_out[g] = red[0] + bout[0];
}

// ---------------- emit: kernel copy into d_out (graph-capture safe) ----------
__global__ void k_emit(float* __restrict__ out, int out_size) {
    int i = blockIdx.x * blockDim.x + threadIdx.x;
    if (i >= out_size) return;
    float v;
    if (out_size >= NG + HID) {
        v = (i < NG) ? g_out[i] : g_hidden[i - NG];
    } else if (out_size == HID) {
        v = g_hidden[i];
    } else {
        v = (i < NG) ? g_out[i] : 0.0f;
    }
    out[i] = v;
}

// ---------------- launch -----------------------------------------------------
extern "C" void kernel_launch(void* const* d_in, const int* in_sizes, int n_in,
                              void* d_out, int out_size) {
    const float* x     = (const float*)d_in[0];
    const int*   ei    = (const int*)d_in[1];      // int32
    const int*   batch = (const int*)d_in[2];      // int32
    const float* ew    = (const float*)d_in[3];
    const float* W[4] = { (const float*)d_in[4], (const float*)d_in[6],
                          (const float*)d_in[8], (const float*)d_in[10] };
    const float* B[4] = { (const float*)d_in[5], (const float*)d_in[7],
                          (const float*)d_in[9], (const float*)d_in[11] };
    const float* Wout = (const float*)d_in[12];
    const float* bout = (const float*)d_in[13];

    cudaFuncSetAttribute(k_gemm, cudaFuncAttributeMaxDynamicSharedMemorySize, GEMM_SMEM);

    float *tbuf, *hA, *hB;
    cudaGetSymbolAddress((void**)&tbuf, g_t);
    cudaGetSymbolAddress((void**)&hA, g_hA);
    cudaGetSymbolAddress((void**)&hB, g_hB);

    k_init<<<(NN + 255) / 256, 256>>>();
    k_deg<<<(NE + 255) / 256, 256>>>(ei, ew);
    k_dinv<<<(NN + 255) / 256, 256>>>();
    k_bsum<<<NBLK, SCAN_B>>>();
    k_bscan<<<1, SCAN_B>>>();
    k_ptr<<<NBLK, SCAN_B>>>();
    k_scatter<<<(NE + 255) / 256, 256>>>(ei, ew);
    k_bounds<<<(NN + 255) / 256, 256>>>(batch);

    const int gemm_grid = (NN + 63) / 64;
    const int aggr_grid = (NN * 32 + 255) / 256;

    const float* cur = x;
    float* ping[4] = { hA, hB, hA, hB };
    for (int l = 0; l < 4; l++) {
        k_gemm<<<gemm_grid, 256, GEMM_SMEM>>>(cur, W[l], tbuf, NN);
        k_aggr<<<aggr_grid, 256>>>(tbuf, B[l], ping[l]);
        cur = ping[l];
    }

    k_readout<<<NG, 128>>>(cur);
    k_final<<<NG, 256>>>(Wout, bout);
    k_emit<<<(out_size + 255) / 256, 256>>>((float*)d_out, out_size);
}

// round 6
// speedup vs baseline: 1.2931x; 1.0896x over previous
#include <cuda_runtime.h>
#include <math.h>

#define NN 50000
#define NE 600000
#define HD 128
#define NG 64
#define HID (NG * 256)
#define SCAN_B 256
#define NBLK ((NN + SCAN_B - 1) / SCAN_B)   // 196

// ---------------- scratch (static device globals; no runtime allocation) ----
__device__ __align__(16) float g_deg[NN];
__device__ __align__(16) float g_self[NN];
__device__ __align__(16) int   g_cnt[NN];
__device__ __align__(16) int   g_ptr[NN + 1];
__device__ __align__(16) int   g_cur[NN];
__device__ __align__(16) int   g_bsum[NBLK];
__device__ __align__(16) int   g_boff[NBLK];
__device__ __align__(16) int   g_srcA[NE];
__device__ __align__(16) float g_normA[NE];
__device__ __align__(16) float g_t[(size_t)NN * HD];
__device__ __align__(16) float g_hA[(size_t)NN * HD];
__device__ __align__(16) float g_hB[(size_t)NN * HD];
__device__ __align__(16) float g_hidden[HID];
__device__ __align__(16) float g_out[NG];
__device__ int g_gs[NG], g_ge[NG];

// ---------------- setup kernels ---------------------------------------------
__global__ void k_init() {
    int i = blockIdx.x * blockDim.x + threadIdx.x;
    if (i < NN) { g_deg[i] = 2.0f; g_cnt[i] = 0; }
    if (i < NG) { g_gs[i] = 0; g_ge[i] = 0; }
}

__global__ void k_deg(const int* __restrict__ ei, const float* __restrict__ ew) {
    int i = blockIdx.x * blockDim.x + threadIdx.x;
    if (i >= NE) return;
    int d = ei[NE + i];
    if ((unsigned)d >= NN) return;
    atomicAdd(&g_deg[d], ew[i]);
    atomicAdd(&g_cnt[d], 1);
}

__global__ void k_dinv() {
    int i = blockIdx.x * blockDim.x + threadIdx.x;
    if (i >= NN) return;
    float dv = rsqrtf(g_deg[i]);
    g_deg[i] = dv;
    g_self[i] = 2.0f * dv * dv;
}

// ---------------- 3-phase exclusive scan of g_cnt into g_ptr ----------------
__global__ void k_bsum() {
    __shared__ int sh[SCAN_B];
    int i = blockIdx.x * SCAN_B + threadIdx.x;
    sh[threadIdx.x] = (i < NN) ? g_cnt[i] : 0;
    __syncthreads();
    for (int off = SCAN_B / 2; off > 0; off >>= 1) {
        if (threadIdx.x < off) sh[threadIdx.x] += sh[threadIdx.x + off];
        __syncthreads();
    }
    if (threadIdx.x == 0) g_bsum[blockIdx.x] = sh[0];
}

__global__ void k_bscan() {
    __shared__ int sh[SCAN_B];
    int t = threadIdx.x;
    int v = (t < NBLK) ? g_bsum[t] : 0;
    sh[t] = v;
    __syncthreads();
    for (int off = 1; off < SCAN_B; off <<= 1) {
        int u = (t >= off) ? sh[t - off] : 0;
        __syncthreads();
        sh[t] += u;
        __syncthreads();
    }
    if (t < NBLK) g_boff[t] = sh[t] - v;
    if (t == NBLK - 1) g_ptr[NN] = sh[t];
}

__global__ void k_ptr() {
    __shared__ int sh[SCAN_B];
    int i = blockIdx.x * SCAN_B + threadIdx.x;
    int t = threadIdx.x;
    int v = (i < NN) ? g_cnt[i] : 0;
    sh[t] = v;
    __syncthreads();
    for (int off = 1; off < SCAN_B; off <<= 1) {
        int u = (t >= off) ? sh[t - off] : 0;
        __syncthreads();
        sh[t] += u;
        __syncthreads();
    }
    if (i < NN) {
        int p = g_boff[blockIdx.x] + sh[t] - v;
        g_ptr[i] = p;
        g_cur[i] = p;
    }
}

__global__ void k_scatter(const int* __restrict__ ei, const float* __restrict__ ew) {
    int i = blockIdx.x * blockDim.x + threadIdx.x;
    if (i >= NE) return;
    int s = ei[i];
    int d = ei[NE + i];
    if ((unsigned)s >= NN || (unsigned)d >= NN) return;
    int pos = atomicAdd(&g_cur[d], 1);
    if ((unsigned)pos >= NE) return;
    g_srcA[pos] = s;
    g_normA[pos] = g_deg[s] * ew[i] * g_deg[d];
}

__global__ void k_bounds(const int* __restrict__ batch) {
    int i = blockIdx.x * blockDim.x + threadIdx.x;
    if (i >= NN) return;
    int g = batch[i];
    if ((unsigned)g >= NG) return;
    if (i == 0 || batch[i - 1] != g) g_gs[g] = i;
    if (i == NN - 1 || batch[i + 1] != g) g_ge[g] = i + 1;
}

// ---------------- TF32 tensor-core GEMM: O[n,128] = A[n,128] @ W[128,128] ---
// Block: 256 thr (8 warps), tile 128 rows x 128 cols. mma.m16n8k8 tf32.
#define STRA 132   // A smem stride: (r*132+c)%32 == (r*4+c)%32 -> conflict-free frag loads
#define STRW 136   // W smem stride: (c*136+r)%32 == (c*8+r)%32 -> conflict-free frag loads
#define GEMM_SMEM ((128 * STRW + 128 * STRA) * (int)sizeof(float))

__device__ __forceinline__ unsigned f2tf32(float x) {
    unsigned y;
    asm("cvt.rna.tf32.f32 %0, %1;" : "=r"(y) : "f"(x));
    return y;
}

__device__ __forceinline__ void mma_tf32(float* c, unsigned a0, unsigned a1,
                                         unsigned a2, unsigned a3,
                                         unsigned b0, unsigned b1) {
    asm volatile(
        "mma.sync.aligned.m16n8k8.row.col.f32.tf32.tf32.f32 "
        "{%0,%1,%2,%3}, {%4,%5,%6,%7}, {%8,%9}, {%0,%1,%2,%3};"
        : "+f"(c[0]), "+f"(c[1]), "+f"(c[2]), "+f"(c[3])
        : "r"(a0), "r"(a1), "r"(a2), "r"(a3), "r"(b0), "r"(b1));
}

__global__ __launch_bounds__(256) void k_gemm(const float* __restrict__ A,
                                              const float* __restrict__ W,
                                              float* __restrict__ O, int nrows) {
    extern __shared__ float sm[];
    float* Ws = sm;              // [k=128][STRW], tf32 bits
    float* As = sm + 128 * STRW; // [r=128][STRA], tf32 bits
    const int tid = threadIdx.x;
    const int row0 = blockIdx.x * 128;

    // fill W smem (cvt to tf32), vectorized
    for (int idx = tid; idx < 128 * 128 / 4; idx += 256) {
        int e = idx * 4;
        int k = e >> 7, n = e & 127;
        float4 v = *(const float4*)(W + e);
        float4 t;
        t.x = __uint_as_float(f2tf32(v.x));
        t.y = __uint_as_float(f2tf32(v.y));
        t.z = __uint_as_float(f2tf32(v.z));
        t.w = __uint_as_float(f2tf32(v.w));
        *(float4*)(Ws + k * STRW + n) = t;   // row base 136*4=544B, 16B-aligned
    }
    // fill A smem (cvt to tf32), zero-pad tail rows
    for (int idx = tid; idx < 128 * 128 / 4; idx += 256) {
        int e = idx * 4;
        int r = e >> 7, k = e & 127;
        int gr = row0 + r;
        float4 v = (gr < nrows) ? *(const float4*)(A + (size_t)gr * HD + k)
                                : make_float4(0.f, 0.f, 0.f, 0.f);
        float4 t;
        t.x = __uint_as_float(f2tf32(v.x));
        t.y = __uint_as_float(f2tf32(v.y));
        t.z = __uint_as_float(f2tf32(v.z));
        t.w = __uint_as_float(f2tf32(v.w));
        *(float4*)(As + r * STRA + k) = t;   // row base 132*4=528B, 16B-aligned
    }
    __syncthreads();

    const int wid = tid >> 5, lane = tid & 31;
    const int r = lane >> 2;     // 0..7
    const int c = lane & 3;      // 0..3
    const int warpRow = wid * 16;

    float acc[16][4];
#pragma unroll
    for (int nt = 0; nt < 16; nt++) {
        acc[nt][0] = 0.f; acc[nt][1] = 0.f; acc[nt][2] = 0.f; acc[nt][3] = 0.f;
    }

#pragma unroll
    for (int k0 = 0; k0 < 128; k0 += 8) {
        unsigned a0 = __float_as_uint(As[(warpRow + r) * STRA + k0 + c]);
        unsigned a1 = __float_as_uint(As[(warpRow + r + 8) * STRA + k0 + c]);
        unsigned a2 = __float_as_uint(As[(warpRow + r) * STRA + k0 + c + 4]);
        unsigned a3 = __float_as_uint(As[(warpRow + r + 8) * STRA + k0 + c + 4]);
#pragma unroll
        for (int nt = 0; nt < 16; nt++) {
            int n0 = nt * 8;
            unsigned b0 = __float_as_uint(Ws[(k0 + c) * STRW + n0 + r]);
            unsigned b1 = __float_as_uint(Ws[(k0 + 4 + c) * STRW + n0 + r]);
            mma_tf32(acc[nt], a0, a1, a2, a3, b0, b1);
        }
    }

    // epilogue: c0/c1 at (row, (c*2, c*2+1)), c2/c3 at (row+8, ...)
    int orowA = row0 + warpRow + r;
    int orowB = orowA + 8;
#pragma unroll
    for (int nt = 0; nt < 16; nt++) {
        int n = nt * 8 + c * 2;
        if (orowA < nrows)
            *(float2*)(O + (size_t)orowA * HD + n) = make_float2(acc[nt][0], acc[nt][1]);
        if (orowB < nrows)
            *(float2*)(O + (size_t)orowB * HD + n) = make_float2(acc[nt][2], acc[nt][3]);
    }
}

// ---------------- aggregation: one warp per destination node ----------------
__global__ void k_aggr(const float* __restrict__ T, const float* __restrict__ bias,
                       float* __restrict__ Hout) {
    int gw = (blockIdx.x * blockDim.x + threadIdx.x) >> 5;
    if (gw >= NN) return;
    const int lane = threadIdx.x & 31;
    const int c = lane << 2;

    float sn = g_self[gw];
    float4 t0 = *(const float4*)(T + (size_t)gw * HD + c);
    float4 acc = make_float4(t0.x * sn, t0.y * sn, t0.z * sn, t0.w * sn);

    int e = g_ptr[gw];
    const int e1 = g_ptr[gw + 1];
    for (; e + 3 < e1; e += 4) {
        int s0 = g_srcA[e], s1 = g_srcA[e + 1], s2 = g_srcA[e + 2], s3 = g_srcA[e + 3];
        float w0 = g_normA[e], w1 = g_normA[e + 1], w2 = g_normA[e + 2], w3 = g_normA[e + 3];
        float4 v0 = *(const float4*)(T + (size_t)s0 * HD + c);
        float4 v1 = *(const float4*)(T + (size_t)s1 * HD + c);
        float4 v2 = *(const float4*)(T + (size_t)s2 * HD + c);
        float4 v3 = *(const float4*)(T + (size_t)s3 * HD + c);
        acc.x += w0 * v0.x + w1 * v1.x + w2 * v2.x + w3 * v3.x;
        acc.y += w0 * v0.y + w1 * v1.y + w2 * v2.y + w3 * v3.y;
        acc.z += w0 * v0.z + w1 * v1.z + w2 * v2.z + w3 * v3.z;
        acc.w += w0 * v0.w + w1 * v1.w + w2 * v2.w + w3 * v3.w;
    }
    for (; e < e1; e++) {
        int s = g_srcA[e];
        float w = g_normA[e];
        float4 v = *(const float4*)(T + (size_t)s * HD + c);
        acc.x += w * v.x; acc.y += w * v.y; acc.z += w * v.z; acc.w += w * v.w;
    }
    float4 bb = *(const float4*)(bias + c);
    float4 o;
    o.x = tanhf(acc.x + bb.x);
    o.y = tanhf(acc.y + bb.y);
    o.z = tanhf(acc.z + bb.z);
    o.w = tanhf(acc.w + bb.w);
    *(float4*)(Hout + (size_t)gw * HD + c) = o;
}

// ---------------- readout ----------------------------------------------------
__global__ void k_readout(const float* __restrict__ Hl) {
    int g = blockIdx.x;
    int c = threadIdx.x;   // 128
    int s = g_gs[g], e = g_ge[g];
    float vmax = -INFINITY, vsum = 0.0f;
    for (int i = s; i < e; i++) {
        float v = Hl[(size_t)i * HD + c];
        vmax = fmaxf(vmax, v);
        vsum += v;
    }
    int cnt = e - s;
    g_hidden[(size_t)g * 256 + c] = (cnt > 0) ? vmax : 0.0f;
    g_hidden[(size_t)g * 256 + 128 + c] = vsum / fmaxf((float)cnt, 1.0f);
}

__global__ void k_final(const float* __restrict__ Wout, const float* __restrict__ bout) {
    __shared__ float red[256];
    int g = blockIdx.x, t = threadIdx.x;
    red[t] = g_hidden[(size_t)g * 256 + t] * Wout[t];
    __syncthreads();
    for (int off = 128; off > 0; off >>= 1) {
        if (t < off) red[t] += red[t + off];
        __syncthreads();
    }
    if (t == 0) g_out[g] = red[0] + bout[0];
}

// ---------------- emit -------------------------------------------------------
__global__ void k_emit(float* __restrict__ out, int out_size) {
    int i = blockIdx.x * blockDim.x + threadIdx.x;
    if (i >= out_size) return;
    float v;
    if (out_size >= NG + HID) {
        v = (i < NG) ? g_out[i] : g_hidden[i - NG];
    } else if (out_size == HID) {
        v = g_hidden[i];
    } else {
        v = (i < NG) ? g_out[i] : 0.0f;
    }
    out[i] = v;
}

// ---------------- launch -----------------------------------------------------
extern "C" void kernel_launch(void* const* d_in, const int* in_sizes, int n_in,
                              void* d_out, int out_size) {
    const float* x     = (const float*)d_in[0];
    const int*   ei    = (const int*)d_in[1];
    const int*   batch = (const int*)d_in[2];
    const float* ew    = (const float*)d_in[3];
    const float* W[4] = { (const float*)d_in[4], (const float*)d_in[6],
                          (const float*)d_in[8], (const float*)d_in[10] };
    const float* B[4] = { (const float*)d_in[5], (const float*)d_in[7],
                          (const float*)d_in[9], (const float*)d_in[11] };
    const float* Wout = (const float*)d_in[12];
    const float* bout = (const float*)d_in[13];

    cudaFuncSetAttribute(k_gemm, cudaFuncAttributeMaxDynamicSharedMemorySize, GEMM_SMEM);

    float *tbuf, *hA, *hB;
    cudaGetSymbolAddress((void**)&tbuf, g_t);
    cudaGetSymbolAddress((void**)&hA, g_hA);
    cudaGetSymbolAddress((void**)&hB, g_hB);

    k_init<<<(NN + 255) / 256, 256>>>();
    k_deg<<<(NE + 255) / 256, 256>>>(ei, ew);
    k_dinv<<<(NN + 255) / 256, 256>>>();
    k_bsum<<<NBLK, SCAN_B>>>();
    k_bscan<<<1, SCAN_B>>>();
    k_ptr<<<NBLK, SCAN_B>>>();
    k_scatter<<<(NE + 255) / 256, 256>>>(ei, ew);
    k_bounds<<<(NN + 255) / 256, 256>>>(batch);

    const int gemm_grid = (NN + 127) / 128;   // 391
    const int aggr_grid = (NN * 32 + 255) / 256;

    const float* cur = x;
    float* ping[4] = { hA, hB, hA, hB };
    for (int l = 0; l < 4; l++) {
        k_gemm<<<gemm_grid, 256, GEMM_SMEM>>>(cur, W[l], tbuf, NN);
        k_aggr<<<aggr_grid, 256>>>(tbuf, B[l], ping[l]);
        cur = ping[l];
    }

    k_readout<<<NG, 128>>>(cur);
    k_final<<<NG, 256>>>(Wout, bout);
    k_emit<<<(out_size + 255) / 256, 256>>>((float*)d_out, out_size);
}

// round 7
// speedup vs baseline: 1.3619x; 1.0532x over previous
#include <cuda_runtime.h>
#include <cuda_fp16.h>
#include <math.h>

#define NN 50000
#define NE 600000
#define HD 128
#define NG 64
#define HID (NG * 256)
#define SCAN_B 256
#define NBLK ((NN + SCAN_B - 1) / SCAN_B)   // 196

// ---------------- scratch ----------------------------------------------------
__device__ __align__(16) float g_deg[NN];
__device__ __align__(16) float g_self[NN];
__device__ __align__(16) int   g_cnt[NN];
__device__ __align__(16) int   g_ptr[NN + 1];
__device__ __align__(16) int   g_cur[NN];
__device__ __align__(16) int   g_bsum[NBLK];
__device__ __align__(16) int   g_boff[NBLK];
__device__ __align__(16) int   g_srcA[NE];
__device__ __align__(16) float g_normA[NE];
__device__ __align__(16) __half g_t[(size_t)NN * HD];   // GEMM out, fp16 (gathered)
__device__ __align__(16) float g_hA[(size_t)NN * HD];
__device__ __align__(16) float g_hB[(size_t)NN * HD];
__device__ __align__(16) float g_hidden[HID];
__device__ __align__(16) float g_out[NG];
__device__ int g_gs[NG], g_ge[NG];

// ---------------- setup kernels ---------------------------------------------
__global__ void k_init() {
    int i = blockIdx.x * blockDim.x + threadIdx.x;
    if (i < NN) { g_deg[i] = 2.0f; g_cnt[i] = 0; }
    if (i < NG) { g_gs[i] = 0; g_ge[i] = 0; }
}

__global__ void k_deg(const int* __restrict__ ei, const float* __restrict__ ew) {
    int i = blockIdx.x * blockDim.x + threadIdx.x;
    if (i >= NE) return;
    int d = ei[NE + i];
    if ((unsigned)d >= NN) return;
    atomicAdd(&g_deg[d], ew[i]);
    atomicAdd(&g_cnt[d], 1);
}

// block-sum of counts + dinv/self (fused; both depend only on k_deg)
__global__ void k_bsum() {
    __shared__ int sh[SCAN_B];
    int i = blockIdx.x * SCAN_B + threadIdx.x;
    if (i < NN) {
        float dv = rsqrtf(g_deg[i]);   // deg >= 2 always
        g_deg[i] = dv;
        g_self[i] = 2.0f * dv * dv;
    }
    sh[threadIdx.x] = (i < NN) ? g_cnt[i] : 0;
    __syncthreads();
    for (int off = SCAN_B / 2; off > 0; off >>= 1) {
        if (threadIdx.x < off) sh[threadIdx.x] += sh[threadIdx.x + off];
        __syncthreads();
    }
    if (threadIdx.x == 0) g_bsum[blockIdx.x] = sh[0];
}

__global__ void k_bscan() {
    __shared__ int sh[SCAN_B];
    int t = threadIdx.x;
    int v = (t < NBLK) ? g_bsum[t] : 0;
    sh[t] = v;
    __syncthreads();
    for (int off = 1; off < SCAN_B; off <<= 1) {
        int u = (t >= off) ? sh[t - off] : 0;
        __syncthreads();
        sh[t] += u;
        __syncthreads();
    }
    if (t < NBLK) g_boff[t] = sh[t] - v;
    if (t == NBLK - 1) g_ptr[NN] = sh[t];
}

// row pointers + graph bounds (fused)
__global__ void k_ptr(const int* __restrict__ batch) {
    __shared__ int sh[SCAN_B];
    int i = blockIdx.x * SCAN_B + threadIdx.x;
    int t = threadIdx.x;
    int v = (i < NN) ? g_cnt[i] : 0;
    sh[t] = v;
    __syncthreads();
    for (int off = 1; off < SCAN_B; off <<= 1) {
        int u = (t >= off) ? sh[t - off] : 0;
        __syncthreads();
        sh[t] += u;
        __syncthreads();
    }
    if (i < NN) {
        int p = g_boff[blockIdx.x] + sh[t] - v;
        g_ptr[i] = p;
        g_cur[i] = p;
        int g = batch[i];
        if ((unsigned)g < NG) {
            if (i == 0 || batch[i - 1] != g) g_gs[g] = i;
            if (i == NN - 1 || batch[i + 1] != g) g_ge[g] = i + 1;
        }
    }
}

__global__ void k_scatter(const int* __restrict__ ei, const float* __restrict__ ew) {
    int i = blockIdx.x * blockDim.x + threadIdx.x;
    if (i >= NE) return;
    int s = ei[i];
    int d = ei[NE + i];
    if ((unsigned)s >= NN || (unsigned)d >= NN) return;
    int pos = atomicAdd(&g_cur[d], 1);
    if ((unsigned)pos >= NE) return;
    g_srcA[pos] = s;
    g_normA[pos] = g_deg[s] * ew[i] * g_deg[d];
}

// ---------------- TF32 tensor-core GEMM -> fp16 output ----------------------
#define STRA 132
#define STRW 136
#define GEMM_SMEM ((128 * STRW + 128 * STRA) * (int)sizeof(float))

__device__ __forceinline__ unsigned f2tf32(float x) {
    unsigned y;
    asm("cvt.rna.tf32.f32 %0, %1;" : "=r"(y) : "f"(x));
    return y;
}

__device__ __forceinline__ void mma_tf32(float* c, unsigned a0, unsigned a1,
                                         unsigned a2, unsigned a3,
                                         unsigned b0, unsigned b1) {
    asm volatile(
        "mma.sync.aligned.m16n8k8.row.col.f32.tf32.tf32.f32 "
        "{%0,%1,%2,%3}, {%4,%5,%6,%7}, {%8,%9}, {%0,%1,%2,%3};"
        : "+f"(c[0]), "+f"(c[1]), "+f"(c[2]), "+f"(c[3])
        : "r"(a0), "r"(a1), "r"(a2), "r"(a3), "r"(b0), "r"(b1));
}

__global__ __launch_bounds__(256) void k_gemm(const float* __restrict__ A,
                                              const float* __restrict__ W,
                                              __half* __restrict__ O, int nrows) {
    extern __shared__ float sm[];
    float* Ws = sm;              // [k=128][STRW]
    float* As = sm + 128 * STRW; // [r=128][STRA]
    const int tid = threadIdx.x;
    const int row0 = blockIdx.x * 128;

    for (int idx = tid; idx < 128 * 128 / 4; idx += 256) {
        int e = idx * 4;
        int k = e >> 7, n = e & 127;
        float4 v = *(const float4*)(W + e);
        float4 t;
        t.x = __uint_as_float(f2tf32(v.x));
        t.y = __uint_as_float(f2tf32(v.y));
        t.z = __uint_as_float(f2tf32(v.z));
        t.w = __uint_as_float(f2tf32(v.w));
        *(float4*)(Ws + k * STRW + n) = t;
    }
    for (int idx = tid; idx < 128 * 128 / 4; idx += 256) {
        int e = idx * 4;
        int r = e >> 7, k = e & 127;
        int gr = row0 + r;
        float4 v = (gr < nrows) ? *(const float4*)(A + (size_t)gr * HD + k)
                                : make_float4(0.f, 0.f, 0.f, 0.f);
        float4 t;
        t.x = __uint_as_float(f2tf32(v.x));
        t.y = __uint_as_float(f2tf32(v.y));
        t.z = __uint_as_float(f2tf32(v.z));
        t.w = __uint_as_float(f2tf32(v.w));
        *(float4*)(As + r * STRA + k) = t;
    }
    __syncthreads();

    const int wid = tid >> 5, lane = tid & 31;
    const int r = lane >> 2;
    const int c = lane & 3;
    const int warpRow = wid * 16;

    float acc[16][4];
#pragma unroll
    for (int nt = 0; nt < 16; nt++) {
        acc[nt][0] = 0.f; acc[nt][1] = 0.f; acc[nt][2] = 0.f; acc[nt][3] = 0.f;
    }

#pragma unroll
    for (int k0 = 0; k0 < 128; k0 += 8) {
        unsigned a0 = __float_as_uint(As[(warpRow + r) * STRA + k0 + c]);
        unsigned a1 = __float_as_uint(As[(warpRow + r + 8) * STRA + k0 + c]);
        unsigned a2 = __float_as_uint(As[(warpRow + r) * STRA + k0 + c + 4]);
        unsigned a3 = __float_as_uint(As[(warpRow + r + 8) * STRA + k0 + c + 4]);
#pragma unroll
        for (int nt = 0; nt < 16; nt++) {
            int n0 = nt * 8;
            unsigned b0 = __float_as_uint(Ws[(k0 + c) * STRW + n0 + r]);
            unsigned b1 = __float_as_uint(Ws[(k0 + 4 + c) * STRW + n0 + r]);
            mma_tf32(acc[nt], a0, a1, a2, a3, b0, b1);
        }
    }

    int orowA = row0 + warpRow + r;
    int orowB = orowA + 8;
#pragma unroll
    for (int nt = 0; nt < 16; nt++) {
        int n = nt * 8 + c * 2;
        if (orowA < nrows)
            *(__half2*)(O + (size_t)orowA * HD + n) =
                __floats2half2_rn(acc[nt][0], acc[nt][1]);
        if (orowB < nrows)
            *(__half2*)(O + (size_t)orowB * HD + n) =
                __floats2half2_rn(acc[nt][2], acc[nt][3]);
    }
}

// ---------------- aggregation: one warp per destination, fp16 gather --------
__global__ void k_aggr(const __half* __restrict__ T, const float* __restrict__ bias,
                       float* __restrict__ Hout) {
    int gw = (blockIdx.x * blockDim.x + threadIdx.x) >> 5;
    if (gw >= NN) return;
    const int lane = threadIdx.x & 31;
    const int c = lane << 2;     // 4 halves per lane = 8 bytes (uint2)

    float sn = g_self[gw];
    uint2 tr = *(const uint2*)(T + (size_t)gw * HD + c);
    float2 ta = __half22float2(*(__half2*)&tr.x);
    float2 tb = __half22float2(*(__half2*)&tr.y);
    float4 acc = make_float4(ta.x * sn, ta.y * sn, tb.x * sn, tb.y * sn);

    int e = g_ptr[gw];
    const int e1 = g_ptr[gw + 1];
    for (; e + 3 < e1; e += 4) {
        int s0 = g_srcA[e], s1 = g_srcA[e + 1], s2 = g_srcA[e + 2], s3 = g_srcA[e + 3];
        float w0 = g_normA[e], w1 = g_normA[e + 1], w2 = g_normA[e + 2], w3 = g_normA[e + 3];
        uint2 r0 = *(const uint2*)(T + (size_t)s0 * HD + c);
        uint2 r1 = *(const uint2*)(T + (size_t)s1 * HD + c);
        uint2 r2 = *(const uint2*)(T + (size_t)s2 * HD + c);
        uint2 r3 = *(const uint2*)(T + (size_t)s3 * HD + c);
        float2 a0 = __half22float2(*(__half2*)&r0.x), b0 = __half22float2(*(__half2*)&r0.y);
        float2 a1 = __half22float2(*(__half2*)&r1.x), b1 = __half22float2(*(__half2*)&r1.y);
        float2 a2 = __half22float2(*(__half2*)&r2.x), b2 = __half22float2(*(__half2*)&r2.y);
        float2 a3 = __half22float2(*(__half2*)&r3.x), b3 = __half22float2(*(__half2*)&r3.y);
        acc.x += w0 * a0.x + w1 * a1.x + w2 * a2.x + w3 * a3.x;
        acc.y += w0 * a0.y + w1 * a1.y + w2 * a2.y + w3 * a3.y;
        acc.z += w0 * b0.x + w1 * b1.x + w2 * b2.x + w3 * b3.x;
        acc.w += w0 * b0.y + w1 * b1.y + w2 * b2.y + w3 * b3.y;
    }
    for (; e < e1; e++) {
        int s = g_srcA[e];
        float w = g_normA[e];
        uint2 rr = *(const uint2*)(T + (size_t)s * HD + c);
        float2 aa = __half22float2(*(__half2*)&rr.x);
        float2 bb2 = __half22float2(*(__half2*)&rr.y);
        acc.x += w * aa.x; acc.y += w * aa.y; acc.z += w * bb2.x; acc.w += w * bb2.y;
    }
    float4 bb = *(const float4*)(bias + c);
    float4 o;
    o.x = tanhf(acc.x + bb.x);
    o.y = tanhf(acc.y + bb.y);
    o.z = tanhf(acc.z + bb.z);
    o.w = tanhf(acc.w + bb.w);
    *(float4*)(Hout + (size_t)gw * HD + c) = o;
}

// ---------------- readout ----------------------------------------------------
__global__ void k_readout(const float* __restrict__ Hl) {
    int g = blockIdx.x;
    int c = threadIdx.x;
    int s = g_gs[g], e = g_ge[g];
    float vmax = -INFINITY, vsum = 0.0f;
    for (int i = s; i < e; i++) {
        float v = Hl[(size_t)i * HD + c];
        vmax = fmaxf(vmax, v);
        vsum += v;
    }
    int cnt = e - s;
    g_hidden[(size_t)g * 256 + c] = (cnt > 0) ? vmax : 0.0f;
    g_hidden[(size_t)g * 256 + 128 + c] = vsum / fmaxf((float)cnt, 1.0f);
}

__global__ void k_final(const float* __restrict__ Wout, const float* __restrict__ bout) {
    __shared__ float red[256];
    int g = blockIdx.x, t = threadIdx.x;
    red[t] = g_hidden[(size_t)g * 256 + t] * Wout[t];
    __syncthreads();
    for (int off = 128; off > 0; off >>= 1) {
        if (t < off) red[t] += red[t + off];
        __syncthreads();
    }
    if (t == 0) g_out[g] = red[0] + bout[0];
}

// ---------------- emit -------------------------------------------------------
__global__ void k_emit(float* __restrict__ out, int out_size) {
    int i = blockIdx.x * blockDim.x + threadIdx.x;
    if (i >= out_size) return;
    float v;
    if (out_size >= NG + HID) {
        v = (i < NG) ? g_out[i] : g_hidden[i - NG];
    } else if (out_size == HID) {
        v = g_hidden[i];
    } else {
        v = (i < NG) ? g_out[i] : 0.0f;
    }
    out[i] = v;
}

// ---------------- launch -----------------------------------------------------
extern "C" void kernel_launch(void* const* d_in, const int* in_sizes, int n_in,
                              void* d_out, int out_size) {
    const float* x     = (const float*)d_in[0];
    const int*   ei    = (const int*)d_in[1];
    const int*   batch = (const int*)d_in[2];
    const float* ew    = (const float*)d_in[3];
    const float* W[4] = { (const float*)d_in[4], (const float*)d_in[6],
                          (const float*)d_in[8], (const float*)d_in[10] };
    const float* B[4] = { (const float*)d_in[5], (const float*)d_in[7],
                          (const float*)d_in[9], (const float*)d_in[11] };
    const float* Wout = (const float*)d_in[12];
    const float* bout = (const float*)d_in[13];

    cudaFuncSetAttribute(k_gemm, cudaFuncAttributeMaxDynamicSharedMemorySize, GEMM_SMEM);

    __half* tbuf;
    float *hA, *hB;
    cudaGetSymbolAddress((void**)&tbuf, g_t);
    cudaGetSymbolAddress((void**)&hA, g_hA);
    cudaGetSymbolAddress((void**)&hB, g_hB);

    k_init<<<(NN + 255) / 256, 256>>>();
    k_deg<<<(NE + 255) / 256, 256>>>(ei, ew);
    k_bsum<<<NBLK, SCAN_B>>>();
    k_bscan<<<1, SCAN_B>>>();
    k_ptr<<<NBLK, SCAN_B>>>(batch);
    k_scatter<<<(NE + 255) / 256, 256>>>(ei, ew);

    const int gemm_grid = (NN + 127) / 128;   // 391
    const int aggr_grid = (NN * 32 + 255) / 256;

    const float* cur = x;
    float* ping[4] = { hA, hB, hA, hB };
    for (int l = 0; l < 4; l++) {
        k_gemm<<<gemm_grid, 256, GEMM_SMEM>>>(cur, W[l], tbuf, NN);
        k_aggr<<<aggr_grid, 256>>>(tbuf, B[l], ping[l]);
        cur = ping[l];
    }

    k_readout<<<NG, 128>>>(cur);
    k_final<<<NG, 256>>>(Wout, bout);
    k_emit<<<(out_size + 255) / 256, 256>>>((float*)d_out, out_size);
}